// round 16
// baseline (speedup 1.0000x reference)
#include <cuda_runtime.h>
#include <cuda_fp16.h>

#define NN 50000
#define EE 1600000
#define NG 128
#define CSRMAX (EE + NN)   // room for <=1 padding entry per row

// ---------------- device scratch (no allocations allowed) ----------------
__device__ __align__(16)  int      g_deg[NN];
__device__ __align__(16)  int      g_rowcnt[NN];
__device__ __align__(16)  int      g_fill[NN];
__device__ __align__(16)  float    g_dinv[NN];
__device__ __align__(16)  int      g_rowptr[NN + 1];
__device__ __align__(16)  int      g_bsum[64];
// packed CSR entry: low 16 bits = src node id (<65536), high 16 bits = fp16 weight
// rows padded to EVEN length with zero entries (src=0, w=+0 -> exact no-op)
__device__ __align__(16)  unsigned g_csr[CSRMAX];
// layer-1 fp32 T buffers (F=4)
__device__ __align__(128) float    g_t32A[(size_t)NN * 4];
__device__ __align__(128) float    g_t32B[(size_t)NN * 4];
__device__ __align__(128) float    g_t32C[(size_t)NN * 4];
// fp16 feature tables (layers 2/3 + hidden states)
__device__ __align__(128) __half   g_txA[(size_t)NN * 64];
__device__ __align__(128) __half   g_txB[(size_t)NN * 64];
__device__ __align__(128) __half   g_txC[(size_t)NN * 64];
__device__ __align__(128) __half   g_txD[(size_t)NN * 64];
__device__ __align__(128) __half   g_h1 [(size_t)NN * 64];   // 32 used
__device__ __align__(128) __half   g_h2 [(size_t)NN * 64];
__device__ __align__(16)  float    g_pool[NG * 64];
__device__ __align__(16)  int      g_cnt[NG];

// ---------------- packed f32x2 helpers (FFMA2) ----------------
__device__ __forceinline__ unsigned long long pk2(float x, float y) {
    unsigned long long r;
    asm("mov.b64 %0, {%1, %2};" : "=l"(r) : "f"(x), "f"(y));
    return r;
}
__device__ __forceinline__ void fma2(unsigned long long& a, unsigned long long w,
                                     unsigned long long t) {
    asm("fma.rn.f32x2 %0, %1, %2, %0;" : "+l"(a) : "l"(w), "l"(t));
}
__device__ __forceinline__ float2 up2(unsigned long long a) {
    float2 r;
    asm("mov.b64 {%0, %1}, %2;" : "=f"(r.x), "=f"(r.y) : "l"(a));
    return r;
}
__device__ __forceinline__ float2 h2f(unsigned int h) {
    __half2 hh = *reinterpret_cast<__half2*>(&h);
    return __half22float2(hh);
}
__device__ __forceinline__ unsigned int f2h(float2 f) {
    __half2 hh = __float22half2_rn(f);
    return *reinterpret_cast<unsigned int*>(&hh);
}
// decode packed csr entry -> (src, weight)
__device__ __forceinline__ void dec(unsigned e, int& s, float& w) {
    s = (int)(e & 0xFFFFu);
    w = __half2float(__ushort_as_half((unsigned short)(e >> 16)));
}
// L2-only (no L1 allocation) gather loads — random accesses have ~2% L1 hit
// rate; keeping them out of L1 preserves it for the CSR / t0 streams.
__device__ __forceinline__ uint4 ldcg4(const uint4* p) {
    uint4 v;
    asm("ld.global.cg.v4.u32 {%0,%1,%2,%3}, [%4];"
        : "=r"(v.x), "=r"(v.y), "=r"(v.z), "=r"(v.w) : "l"(p));
    return v;
}
__device__ __forceinline__ float4 ldcg4f(const float4* p) {
    float4 v;
    asm("ld.global.cg.v4.f32 {%0,%1,%2,%3}, [%4];"
        : "=f"(v.x), "=f"(v.y), "=f"(v.z), "=f"(v.w) : "l"(p));
    return v;
}
// streaming (evict-first) stores for single-use outputs
__device__ __forceinline__ void stcs4(uint4* p, uint4 v) {
    asm volatile("st.global.cs.v4.u32 [%0], {%1,%2,%3,%4};"
                 :: "l"(p), "r"(v.x), "r"(v.y), "r"(v.z), "r"(v.w) : "memory");
}
__device__ __forceinline__ void stcs4f(float4* p, float4 v) {
    asm volatile("st.global.cs.v4.f32 [%0], {%1,%2,%3,%4};"
                 :: "l"(p), "f"(v.x), "f"(v.y), "f"(v.z), "f"(v.w) : "memory");
}
// accumulate 8 fp16 features (uint4) * w into 4 packed accumulators
__device__ __forceinline__ void acc8(unsigned long long& a0, unsigned long long& a1,
                                     unsigned long long& a2, unsigned long long& a3,
                                     uint4 v, float w) {
    unsigned long long wp = pk2(w, w);
    float2 f0 = h2f(v.x), f1 = h2f(v.y), f2 = h2f(v.z), f3 = h2f(v.w);
    fma2(a0, wp, pk2(f0.x, f0.y));
    fma2(a1, wp, pk2(f1.x, f1.y));
    fma2(a2, wp, pk2(f2.x, f2.y));
    fma2(a3, wp, pk2(f3.x, f3.y));
}

// ---------------- preprocessing ----------------
__global__ void k_zero(int n) {
    int i = blockIdx.x * blockDim.x + threadIdx.x;
    if (i < n) { g_deg[i] = 0; g_rowcnt[i] = 0; }
    if (i < NG * 64) g_pool[i] = 0.f;
    if (i < NG) g_cnt[i] = 0;
}

// 4 edges per thread, int4-vectorized edge_index reads
__global__ void k_count(const int* __restrict__ ei, int E, int n) {
    int q = blockIdx.x * blockDim.x + threadIdx.x;
    int e = q * 4;
    if (e >= E) return;
    if (e + 4 <= E) {
        int4 sv = *(const int4*)(ei + e);
        int4 dv = *(const int4*)(ei + E + e);
        int ss[4] = {sv.x, sv.y, sv.z, sv.w};
        int dd[4] = {dv.x, dv.y, dv.z, dv.w};
#pragma unroll
        for (int j = 0; j < 4; ++j) {
            int s = ss[j], d = dd[j];
            if ((unsigned)s >= (unsigned)n || (unsigned)d >= (unsigned)n) continue;
            if (s != d) {
                atomicAdd(&g_deg[s], 1);
                atomicAdd(&g_rowcnt[d], 1);
            }
        }
    } else {
        for (; e < E; ++e) {
            int s = ei[e], d = ei[E + e];
            if ((unsigned)s >= (unsigned)n || (unsigned)d >= (unsigned)n) continue;
            if (s != d) {
                atomicAdd(&g_deg[s], 1);
                atomicAdd(&g_rowcnt[d], 1);
            }
        }
    }
}

// block sums of PADDED rowcnt + dinv + fill reset (merged)
__global__ void k_scanA(int n, int nthreads) {
    __shared__ int sh[256];
    int b = blockIdx.x, t = threadIdx.x;
    int i0 = b * 1024 + t * 4;
    int s = 0;
#pragma unroll
    for (int j = 0; j < 4; ++j)
        if (i0 + j < n) s += (g_rowcnt[i0 + j] + 1) & ~1;   // pad to even
    sh[t] = s;
    for (int i = b * 256 + t; i < n; i += nthreads) {
        int d = g_deg[i];
        g_dinv[i] = (d > 0) ? rsqrtf((float)d) : 0.f;
        g_fill[i] = 0;
    }
    __syncthreads();
    for (int off = 128; off > 0; off >>= 1) {
        if (t < off) sh[t] += sh[t + off];
        __syncthreads();
    }
    if (t == 0) g_bsum[b] = sh[0];
}

// per-block exclusive scan over PADDED counts + write padding zeros
__global__ void k_scanC(int nblocks, int n) {
    __shared__ int sh[256];
    __shared__ int soff;
    int b = blockIdx.x, t = threadIdx.x;
    if (t == 0) {
        int r = 0;
        for (int i = 0; i < b; ++i) r += g_bsum[i];
        soff = r;
    }
    int i0 = b * 1024 + t * 4;
    int v[4], pc[4];
    int s = 0;
#pragma unroll
    for (int j = 0; j < 4; ++j) {
        v[j] = (i0 + j < n) ? g_rowcnt[i0 + j] : 0;
        pc[j] = (v[j] + 1) & ~1;
        s += pc[j];
    }
    sh[t] = s;
    __syncthreads();
    for (int off = 1; off < 256; off <<= 1) {
        int add = (t >= off) ? sh[t - off] : 0;
        __syncthreads();
        sh[t] += add;
        __syncthreads();
    }
    int excl = sh[t] - s + soff;
#pragma unroll
    for (int j = 0; j < 4; ++j) {
        if (i0 + j < n) {
            g_rowptr[i0 + j] = excl;
            if (pc[j] > v[j]) g_csr[excl + v[j]] = 0u;   // padding: src=0, w=+0
        }
        excl += pc[j];
    }
    if (b == nblocks - 1 && t == 255) g_rowptr[n] = soff + sh[255];
}

// 4 edges per thread, int4-vectorized edge_index reads
__global__ void k_scatter(const int* __restrict__ ei, int E, int n) {
    int q = blockIdx.x * blockDim.x + threadIdx.x;
    int e = q * 4;
    if (e >= E) return;
    int ss[4], dd[4];
    int cnt;
    if (e + 4 <= E) {
        int4 sv = *(const int4*)(ei + e);
        int4 dv = *(const int4*)(ei + E + e);
        ss[0] = sv.x; ss[1] = sv.y; ss[2] = sv.z; ss[3] = sv.w;
        dd[0] = dv.x; dd[1] = dv.y; dd[2] = dv.z; dd[3] = dv.w;
        cnt = 4;
    } else {
        cnt = E - e;
        for (int j = 0; j < cnt; ++j) { ss[j] = ei[e + j]; dd[j] = ei[E + e + j]; }
    }
#pragma unroll
    for (int j = 0; j < 4; ++j) {
        if (j >= cnt) break;
        int s = ss[j], d = dd[j];
        if ((unsigned)s >= (unsigned)n || (unsigned)d >= (unsigned)n) continue;
        if (s == d) continue;
        float w = -g_dinv[s] * g_dinv[d];
        unsigned short wh = __half_as_ushort(__float2half_rn(w));
        unsigned enc = (unsigned)s | ((unsigned)wh << 16);
        int pos = g_rowptr[d] + atomicAdd(&g_fill[d], 1);
        g_csr[pos] = enc;
    }
}

// ---------------- fp32 SpMM (layer 1, F=4) standalone: 8-way edge split ----------
// 8 threads per node, interleaved edge split, shuffle-reduced in fp32 (exact).
template <bool RECUR>
__global__ void k_spmm4(float* __restrict__ y, const float* __restrict__ z,
                        const float* __restrict__ t0, int n) {
    int gid = blockIdx.x * blockDim.x + threadIdx.x;
    int node = gid >> 3;
    int sub = gid & 7;
    if (node >= n) return;
    int end = g_rowptr[node + 1];
    float ax = 0.f, ay = 0.f, az = 0.f, aw = 0.f;
    const float4* z4 = (const float4*)z;
    for (int e = g_rowptr[node] + sub; e < end; e += 8) {
        int s; float w;
        dec(__ldg(&g_csr[e]), s, w);
        float4 v = ldcg4f(&z4[s]);
        ax = fmaf(w, v.x, ax); ay = fmaf(w, v.y, ay);
        az = fmaf(w, v.z, az); aw = fmaf(w, v.w, aw);
    }
#pragma unroll
    for (int off = 4; off >= 1; off >>= 1) {
        ax += __shfl_xor_sync(0xffffffffu, ax, off);
        ay += __shfl_xor_sync(0xffffffffu, ay, off);
        az += __shfl_xor_sync(0xffffffffu, az, off);
        aw += __shfl_xor_sync(0xffffffffu, aw, off);
    }
    if (sub != 0) return;
    float4 r;
    if (RECUR) {
        float4 p = __ldg(((const float4*)t0) + node);
        r = make_float4(2.f * ax - p.x, 2.f * ay - p.y, 2.f * az - p.z, 2.f * aw - p.w);
    } else {
        r = make_float4(ax, ay, az, aw);
    }
    stcs4f(((float4*)y) + node, r);
}

// ---------------- fp32 SpMM core (F=4), 1 thread/node (used by fused kernel) ----
__device__ __forceinline__ float4 spmm4_row_rec(const float* __restrict__ z,
                                                float4 t0row, int node) {
    int beg = g_rowptr[node];            // even
    int end = g_rowptr[node + 1];        // even
    float ax = 0.f, ay = 0.f, az = 0.f, aw = 0.f;
    const float4* z4 = (const float4*)z;
    int e = beg;
    if (end - beg >= 4) {
        uint2 ca = __ldg((const uint2*)(g_csr + e));
        uint2 cb = __ldg((const uint2*)(g_csr + e + 2));
        for (; e + 8 <= end; e += 4) {
            int s0, s1, s2, s3; float w0, w1, w2, w3;
            dec(ca.x, s0, w0); dec(ca.y, s1, w1);
            dec(cb.x, s2, w2); dec(cb.y, s3, w3);
            float4 v0 = ldcg4f(&z4[s0]);
            float4 v1 = ldcg4f(&z4[s1]);
            float4 v2 = ldcg4f(&z4[s2]);
            float4 v3 = ldcg4f(&z4[s3]);
            uint2 na = __ldg((const uint2*)(g_csr + e + 4));
            uint2 nb = __ldg((const uint2*)(g_csr + e + 6));
            ax = fmaf(w0, v0.x, ax); ay = fmaf(w0, v0.y, ay);
            az = fmaf(w0, v0.z, az); aw = fmaf(w0, v0.w, aw);
            ax = fmaf(w1, v1.x, ax); ay = fmaf(w1, v1.y, ay);
            az = fmaf(w1, v1.z, az); aw = fmaf(w1, v1.w, aw);
            ax = fmaf(w2, v2.x, ax); ay = fmaf(w2, v2.y, ay);
            az = fmaf(w2, v2.z, az); aw = fmaf(w2, v2.w, aw);
            ax = fmaf(w3, v3.x, ax); ay = fmaf(w3, v3.y, ay);
            az = fmaf(w3, v3.z, az); aw = fmaf(w3, v3.w, aw);
            ca = na; cb = nb;
        }
        int s0, s1, s2, s3; float w0, w1, w2, w3;
        dec(ca.x, s0, w0); dec(ca.y, s1, w1);
        dec(cb.x, s2, w2); dec(cb.y, s3, w3);
        float4 v0 = ldcg4f(&z4[s0]);
        float4 v1 = ldcg4f(&z4[s1]);
        float4 v2 = ldcg4f(&z4[s2]);
        float4 v3 = ldcg4f(&z4[s3]);
        ax = fmaf(w0, v0.x, ax); ay = fmaf(w0, v0.y, ay);
        az = fmaf(w0, v0.z, az); aw = fmaf(w0, v0.w, aw);
        ax = fmaf(w1, v1.x, ax); ay = fmaf(w1, v1.y, ay);
        az = fmaf(w1, v1.z, az); aw = fmaf(w1, v1.w, aw);
        ax = fmaf(w2, v2.x, ax); ay = fmaf(w2, v2.y, ay);
        az = fmaf(w2, v2.z, az); aw = fmaf(w2, v2.w, aw);
        ax = fmaf(w3, v3.x, ax); ay = fmaf(w3, v3.y, ay);
        az = fmaf(w3, v3.z, az); aw = fmaf(w3, v3.w, aw);
        e += 4;
    }
    for (; e < end; ++e) {
        int s; float w;
        dec(__ldg(&g_csr[e]), s, w);
        float4 v = ldcg4f(&z4[s]);
        ax = fmaf(w, v.x, ax); ay = fmaf(w, v.y, ay);
        az = fmaf(w, v.z, az); aw = fmaf(w, v.w, aw);
    }
    return make_float4(2.f * ax - t0row.x, 2.f * ay - t0row.y,
                       2.f * az - t0row.z, 2.f * aw - t0row.w);
}

// ---------------- FUSED layer-1 4th SpMM + dense: h1 = relu(sum_k T_k W1_k + b)
__global__ void __launch_bounds__(256)
k_spmm4_dense(__half* __restrict__ out,
              const float* __restrict__ t0,   // x
              const float* __restrict__ t1,   // txA
              const float* __restrict__ t2,   // txB (recurrence subtrahend)
              const float* __restrict__ t3,   // txC (spmm operand)
              const float* __restrict__ W, const float* __restrict__ bias, int n) {
    constexpr int FIN = 4, FOUT = 32;
    __shared__ float sW[5 * FIN * FOUT];
    for (int i = threadIdx.x; i < 5 * FIN * FOUT; i += 256) sW[i] = W[i];
    __syncthreads();
    int node = blockIdx.x * blockDim.x + threadIdx.x;
    if (node >= n) return;
    float4 T2 = __ldg(((const float4*)t2) + node);
    float4 T4 = spmm4_row_rec(t3, T2, node);
    float4 T[5];
    T[0] = __ldg(((const float4*)t0) + node);
    T[1] = __ldg(((const float4*)t1) + node);
    T[2] = T2;
    T[3] = __ldg(((const float4*)t3) + node);
    T[4] = T4;
    unsigned long long acc[FOUT / 2];
#pragma unroll
    for (int j = 0; j < FOUT / 2; ++j) acc[j] = pk2(bias[2 * j], bias[2 * j + 1]);
    const unsigned long long* sW2 = (const unsigned long long*)sW;
#pragma unroll
    for (int k = 0; k < 5; ++k) {
        unsigned long long tb0 = pk2(T[k].x, T[k].x);
        unsigned long long tb1 = pk2(T[k].y, T[k].y);
        unsigned long long tb2 = pk2(T[k].z, T[k].z);
        unsigned long long tb3 = pk2(T[k].w, T[k].w);
        const unsigned long long* w0 = sW2 + (size_t)(k * FIN + 0) * (FOUT / 2);
        const unsigned long long* w1 = sW2 + (size_t)(k * FIN + 1) * (FOUT / 2);
        const unsigned long long* w2 = sW2 + (size_t)(k * FIN + 2) * (FOUT / 2);
        const unsigned long long* w3 = sW2 + (size_t)(k * FIN + 3) * (FOUT / 2);
#pragma unroll
        for (int j = 0; j < FOUT / 2; ++j) {
            fma2(acc[j], w0[j], tb0);
            fma2(acc[j], w1[j], tb1);
            fma2(acc[j], w2[j], tb2);
            fma2(acc[j], w3[j], tb3);
        }
    }
    uint4 o[FOUT / 8];
#pragma unroll
    for (int j = 0; j < FOUT / 2; ++j) {
        float2 v = up2(acc[j]);
        v.x = fmaxf(v.x, 0.f);
        v.y = fmaxf(v.y, 0.f);
        ((unsigned int*)o)[j] = f2h(v);
    }
    uint4* orow = (uint4*)(out + (size_t)node * FOUT);
#pragma unroll
    for (int j4 = 0; j4 < FOUT / 8; ++j4) orow[j4] = o[j4];
}

// ---------------- fp16 SpMM: y = L z  or  2 L z - t0 ----------------
// F/8 lanes per node, one uint4 (16B, 8 halves) per lane. CSR read as aligned
// uint2 pairs (rows even-padded); single-stage csr prefetch pipeline.
// Feature gathers bypass L1 (cg); outputs stored streaming (cs).
template <int F, bool RECUR>
__global__ void k_spmmh(__half* __restrict__ y, const __half* __restrict__ z,
                        const __half* __restrict__ t0, int n) {
    constexpr int L = F / 8;
    int gid = blockIdx.x * blockDim.x + threadIdx.x;
    int node = gid / L;
    int lane = gid - node * L;
    if (node >= n) return;
    int beg = g_rowptr[node];            // even
    int end = g_rowptr[node + 1];        // even
    unsigned long long a0 = 0ull, a1 = 0ull, a2 = 0ull, a3 = 0ull;
    const uint4* z4 = (const uint4*)z;
    int e = beg;
    if (end - beg >= 4) {
        uint2 ca = __ldg((const uint2*)(g_csr + e));
        uint2 cb = __ldg((const uint2*)(g_csr + e + 2));
        for (; e + 8 <= end; e += 4) {
            int s0, s1, s2, s3; float w0, w1, w2, w3;
            dec(ca.x, s0, w0); dec(ca.y, s1, w1);
            dec(cb.x, s2, w2); dec(cb.y, s3, w3);
            uint4 v0 = ldcg4(&z4[(size_t)s0 * L + lane]);
            uint4 v1 = ldcg4(&z4[(size_t)s1 * L + lane]);
            uint4 v2 = ldcg4(&z4[(size_t)s2 * L + lane]);
            uint4 v3 = ldcg4(&z4[(size_t)s3 * L + lane]);
            uint2 na = __ldg((const uint2*)(g_csr + e + 4));
            uint2 nb = __ldg((const uint2*)(g_csr + e + 6));
            acc8(a0, a1, a2, a3, v0, w0);
            acc8(a0, a1, a2, a3, v1, w1);
            acc8(a0, a1, a2, a3, v2, w2);
            acc8(a0, a1, a2, a3, v3, w3);
            ca = na; cb = nb;
        }
        int s0, s1, s2, s3; float w0, w1, w2, w3;
        dec(ca.x, s0, w0); dec(ca.y, s1, w1);
        dec(cb.x, s2, w2); dec(cb.y, s3, w3);
        uint4 v0 = ldcg4(&z4[(size_t)s0 * L + lane]);
        uint4 v1 = ldcg4(&z4[(size_t)s1 * L + lane]);
        uint4 v2 = ldcg4(&z4[(size_t)s2 * L + lane]);
        uint4 v3 = ldcg4(&z4[(size_t)s3 * L + lane]);
        acc8(a0, a1, a2, a3, v0, w0);
        acc8(a0, a1, a2, a3, v1, w1);
        acc8(a0, a1, a2, a3, v2, w2);
        acc8(a0, a1, a2, a3, v3, w3);
        e += 4;
    }
    if (e < end) {                        // exactly 2 remaining (even padding)
        uint2 c = __ldg((const uint2*)(g_csr + e));
        int s0, s1; float w0, w1;
        dec(c.x, s0, w0); dec(c.y, s1, w1);
        uint4 v0 = ldcg4(&z4[(size_t)s0 * L + lane]);
        uint4 v1 = ldcg4(&z4[(size_t)s1 * L + lane]);
        acc8(a0, a1, a2, a3, v0, w0);
        acc8(a0, a1, a2, a3, v1, w1);
    }
    size_t o = (size_t)node * L + lane;
    float2 r0 = up2(a0), r1 = up2(a1), r2 = up2(a2), r3 = up2(a3);
    if (RECUR) {
        uint4 p = __ldg(((const uint4*)t0) + o);
        float2 q0 = h2f(p.x), q1 = h2f(p.y), q2 = h2f(p.z), q3 = h2f(p.w);
        r0.x = 2.f * r0.x - q0.x; r0.y = 2.f * r0.y - q0.y;
        r1.x = 2.f * r1.x - q1.x; r1.y = 2.f * r1.y - q1.y;
        r2.x = 2.f * r2.x - q2.x; r2.y = 2.f * r2.y - q2.y;
        r3.x = 2.f * r3.x - q3.x; r3.y = 2.f * r3.y - q3.y;
    }
    uint4 w;
    w.x = f2h(r0); w.y = f2h(r1); w.z = f2h(r2); w.w = f2h(r3);
    stcs4(((uint4*)y) + o, w);
}

// ---------------- fused 5-term dense, fp16 in: out = relu(sum_k T_k @ W_k + b) ------
// POOL: red.v2 relu(acc) into g_pool / g_cnt (global mean pool), no row store.
template <int FIN, int FOUT, bool POOL>
__global__ void __launch_bounds__(128)
k_dense5h(__half* __restrict__ out,
          const __half* __restrict__ t0, const __half* __restrict__ t1,
          const __half* __restrict__ t2, const __half* __restrict__ t3,
          const __half* __restrict__ t4,
          const float* __restrict__ W, const float* __restrict__ bias,
          const int* __restrict__ batch, int n) {
    __shared__ float sW[FIN * FOUT];
    const __half* tx[5] = {t0, t1, t2, t3, t4};
    int node = blockIdx.x * 128 + threadIdx.x;
    unsigned long long acc[FOUT / 2];
    if (node < n) {
#pragma unroll
        for (int j = 0; j < FOUT / 2; ++j) acc[j] = pk2(bias[2 * j], bias[2 * j + 1]);
    }
#pragma unroll
    for (int k = 0; k < 5; ++k) {
        __syncthreads();
        for (int i = threadIdx.x; i < FIN * FOUT; i += 128) sW[i] = W[k * FIN * FOUT + i];
        __syncthreads();
        if (node < n) {
            const uint4* trow = (const uint4*)(tx[k] + (size_t)node * FIN);
            const unsigned long long* sW2 = (const unsigned long long*)sW;
#pragma unroll 2
            for (int i8 = 0; i8 < FIN / 8; ++i8) {
                uint4 v = __ldg(&trow[i8]);
                float2 f0 = h2f(v.x), f1 = h2f(v.y), f2 = h2f(v.z), f3 = h2f(v.w);
                unsigned long long tb[8];
                tb[0] = pk2(f0.x, f0.x); tb[1] = pk2(f0.y, f0.y);
                tb[2] = pk2(f1.x, f1.x); tb[3] = pk2(f1.y, f1.y);
                tb[4] = pk2(f2.x, f2.x); tb[5] = pk2(f2.y, f2.y);
                tb[6] = pk2(f3.x, f3.x); tb[7] = pk2(f3.y, f3.y);
#pragma unroll
                for (int v8 = 0; v8 < 8; ++v8) {
                    const unsigned long long* wr =
                        sW2 + (size_t)(8 * i8 + v8) * (FOUT / 2);
#pragma unroll
                    for (int j = 0; j < FOUT / 2; ++j) fma2(acc[j], wr[j], tb[v8]);
                }
            }
        }
    }
    if (node >= n) return;
    if (POOL) {
        int g = batch[node];
        if ((unsigned)g >= NG) return;
        float* pg = &g_pool[g * FOUT];
#pragma unroll
        for (int j = 0; j < FOUT / 2; ++j) {
            float2 v = up2(acc[j]);
            float vx = fmaxf(v.x, 0.f);
            float vy = fmaxf(v.y, 0.f);
            asm volatile("red.global.add.v2.f32 [%0], {%1, %2};"
                         :: "l"(pg + 2 * j), "f"(vx), "f"(vy) : "memory");
        }
        atomicAdd(&g_cnt[g], 1);
    } else {
        uint4 o[FOUT / 8];
#pragma unroll
        for (int j = 0; j < FOUT / 2; ++j) {
            float2 v = up2(acc[j]);
            v.x = fmaxf(v.x, 0.f);
            v.y = fmaxf(v.y, 0.f);
            ((unsigned int*)o)[j] = f2h(v);
        }
        uint4* orow = (uint4*)(out + (size_t)node * FOUT);
#pragma unroll
        for (int j4 = 0; j4 < FOUT / 8; ++j4) orow[j4] = o[j4];
    }
}

// ---------------- final MLP over pooled means ----------------
__global__ void k_fc(const float* __restrict__ w1, const float* __restrict__ b1,
                     const float* __restrict__ w2, const float* __restrict__ b2,
                     float* __restrict__ out, int G) {
    int g = threadIdx.x;
    if (g >= G) return;
    float c = (float)g_cnt[g];
    if (c < 1.f) c = 1.f;
    float m[64];
#pragma unroll
    for (int i = 0; i < 64; ++i) m[i] = g_pool[g * 64 + i] / c;
    float o = b2[0];
    for (int j = 0; j < 32; ++j) {
        float a = b1[j];
#pragma unroll
        for (int i = 0; i < 64; ++i) a = fmaf(m[i], w1[i * 32 + j], a);
        a = fmaxf(a, 0.f);
        o = fmaf(a, w2[j], o);
    }
    out[g] = o;
}

// ---------------- host ----------------
extern "C" void kernel_launch(void* const* d_in, const int* in_sizes, int n_in,
                              void* d_out, int out_size) {
    const float* x     = (const float*)d_in[0];
    const int*   ei    = (const int*)d_in[1];     // int32 (JAX x64 disabled)
    const int*   batch = (const int*)d_in[2];

    int wi = 3;
    while (wi < n_in && in_sizes[wi] != 640) ++wi;
    const float* W1   = (const float*)d_in[wi + 0];
    const float* b1   = (const float*)d_in[wi + 1];
    const float* W2   = (const float*)d_in[wi + 2];
    const float* b2   = (const float*)d_in[wi + 3];
    const float* W3   = (const float*)d_in[wi + 4];
    const float* b3   = (const float*)d_in[wi + 5];
    const float* fcw1 = (const float*)d_in[wi + 6];
    const float* fcb1 = (const float*)d_in[wi + 7];
    const float* fcw2 = (const float*)d_in[wi + 8];
    const float* fcb2 = (const float*)d_in[wi + 9];

    int n = in_sizes[0] / 4;
    int E = in_sizes[1] / 2;
    float* out = (float*)d_out;

    float *t32A, *t32B, *t32C;
    __half *txA, *txB, *txC, *txD, *h1, *h2;
    cudaGetSymbolAddress((void**)&t32A, g_t32A);
    cudaGetSymbolAddress((void**)&t32B, g_t32B);
    cudaGetSymbolAddress((void**)&t32C, g_t32C);
    cudaGetSymbolAddress((void**)&txA, g_txA);
    cudaGetSymbolAddress((void**)&txB, g_txB);
    cudaGetSymbolAddress((void**)&txC, g_txC);
    cudaGetSymbolAddress((void**)&txD, g_txD);
    cudaGetSymbolAddress((void**)&h1,  g_h1);
    cudaGetSymbolAddress((void**)&h2,  g_h2);

    const int TB = 256;
    int gN = (n + TB - 1) / TB;
    int gE4 = ((E + 3) / 4 + TB - 1) / TB;   // 4 edges/thread
    int gD = (n + 127) / 128;
    int gScan = (n + 1023) / 1024;

    // ---- preprocessing: degree, dinv, even-padded CSR build ----
    k_zero<<<gN, TB>>>(n);
    k_count<<<gE4, TB>>>(ei, E, n);
    k_scanA<<<gScan, 256>>>(n, gScan * 256);
    k_scanC<<<gScan, 256>>>(gScan, n);
    k_scatter<<<gE4, TB>>>(ei, E, n);

    // ---- layer 1: FIN=4 (fp32), FOUT=32 -> h1 (fp16); 4th SpMM fused with dense ----
    {
        int gS = (n * 8 + TB - 1) / TB;   // 8 edge-split threads per node
        k_spmm4<false><<<gS, TB>>>(t32A, x,    x,    n);
        k_spmm4<true ><<<gS, TB>>>(t32B, t32A, x,    n);
        k_spmm4<true ><<<gS, TB>>>(t32C, t32B, t32A, n);
        k_spmm4_dense<<<gN, TB>>>(h1, x, t32A, t32B, t32C, W1, b1, n);
    }

    // ---- layer 2: FIN=32 (fp16), FOUT=64 -> h2 (fp16) ----
    {
        int gS = (n * 4 + TB - 1) / TB;   // L = 32/8 = 4 lanes/node
        k_spmmh<32, false><<<gS, TB>>>(txA, h1,  h1,  n);
        k_spmmh<32, true ><<<gS, TB>>>(txB, txA, h1,  n);
        k_spmmh<32, true ><<<gS, TB>>>(txC, txB, txA, n);
        k_spmmh<32, true ><<<gS, TB>>>(txD, txC, txB, n);
        k_dense5h<32, 64, false><<<gD, 128>>>(h2, h1, txA, txB, txC, txD, W2, b2, batch, n);
    }

    // ---- layer 3: FIN=64 (fp16), FOUT=64, fused global mean pool ----
    {
        int gS = (n * 8 + TB - 1) / TB;   // L = 64/8 = 8 lanes/node
        k_spmmh<64, false><<<gS, TB>>>(txA, h2,  h2,  n);
        k_spmmh<64, true ><<<gS, TB>>>(txB, txA, h2,  n);
        k_spmmh<64, true ><<<gS, TB>>>(txC, txB, txA, n);
        k_spmmh<64, true ><<<gS, TB>>>(txD, txC, txB, n);
        k_dense5h<64, 64, true><<<gD, 128>>>(nullptr, h2, txA, txB, txC, txD, W3, b3, batch, n);
    }

    // ---- MLP head ----
    k_fc<<<1, 128>>>(fcw1, fcb1, fcw2, fcb2, out, out_size);
}

// round 17
// speedup vs baseline: 1.0164x; 1.0164x over previous
#include <cuda_runtime.h>
#include <cuda_fp16.h>

#define NN 50000
#define EE 1600000
#define NG 128
#define CSRMAX (EE + NN)   // room for <=1 padding entry per row

// ---------------- device scratch (no allocations allowed) ----------------
__device__ __align__(16)  int      g_deg[NN];
__device__ __align__(16)  int      g_rowcnt[NN];
__device__ __align__(16)  int      g_fill[NN];
__device__ __align__(16)  float    g_dinv[NN];
__device__ __align__(16)  int      g_rowptr[NN + 1];
__device__ __align__(16)  int      g_bsum[64];
// packed CSR entry: low 16 bits = src node id (<65536), high 16 bits = fp16 weight
// rows padded to EVEN length with zero entries (src=0, w=+0 -> exact no-op)
__device__ __align__(16)  unsigned g_csr[CSRMAX];
// layer-1 fp32 T buffers (F=4)
__device__ __align__(128) float    g_t32A[(size_t)NN * 4];
__device__ __align__(128) float    g_t32B[(size_t)NN * 4];
__device__ __align__(128) float    g_t32C[(size_t)NN * 4];
// fp16 feature tables (layers 2/3 + hidden states)
__device__ __align__(128) __half   g_txA[(size_t)NN * 64];
__device__ __align__(128) __half   g_txB[(size_t)NN * 64];
__device__ __align__(128) __half   g_txC[(size_t)NN * 64];
__device__ __align__(128) __half   g_txD[(size_t)NN * 64];
__device__ __align__(128) __half   g_h1 [(size_t)NN * 64];   // 32 used
__device__ __align__(128) __half   g_h2 [(size_t)NN * 64];
__device__ __align__(16)  float    g_pool[NG * 64];
__device__ __align__(16)  int      g_cnt[NG];

// ---------------- packed f32x2 helpers (FFMA2) ----------------
__device__ __forceinline__ unsigned long long pk2(float x, float y) {
    unsigned long long r;
    asm("mov.b64 %0, {%1, %2};" : "=l"(r) : "f"(x), "f"(y));
    return r;
}
__device__ __forceinline__ void fma2(unsigned long long& a, unsigned long long w,
                                     unsigned long long t) {
    asm("fma.rn.f32x2 %0, %1, %2, %0;" : "+l"(a) : "l"(w), "l"(t));
}
__device__ __forceinline__ float2 up2(unsigned long long a) {
    float2 r;
    asm("mov.b64 {%0, %1}, %2;" : "=f"(r.x), "=f"(r.y) : "l"(a));
    return r;
}
__device__ __forceinline__ float2 h2f(unsigned int h) {
    __half2 hh = *reinterpret_cast<__half2*>(&h);
    return __half22float2(hh);
}
__device__ __forceinline__ unsigned int f2h(float2 f) {
    __half2 hh = __float22half2_rn(f);
    return *reinterpret_cast<unsigned int*>(&hh);
}
// decode packed csr entry -> (src, weight)
__device__ __forceinline__ void dec(unsigned e, int& s, float& w) {
    s = (int)(e & 0xFFFFu);
    w = __half2float(__ushort_as_half((unsigned short)(e >> 16)));
}
// accumulate 8 fp16 features (uint4) * w into 4 packed accumulators
__device__ __forceinline__ void acc8(unsigned long long& a0, unsigned long long& a1,
                                     unsigned long long& a2, unsigned long long& a3,
                                     uint4 v, float w) {
    unsigned long long wp = pk2(w, w);
    float2 f0 = h2f(v.x), f1 = h2f(v.y), f2 = h2f(v.z), f3 = h2f(v.w);
    fma2(a0, wp, pk2(f0.x, f0.y));
    fma2(a1, wp, pk2(f1.x, f1.y));
    fma2(a2, wp, pk2(f2.x, f2.y));
    fma2(a3, wp, pk2(f3.x, f3.y));
}

// ---------------- preprocessing ----------------
__global__ void k_zero(int n) {
    int i = blockIdx.x * blockDim.x + threadIdx.x;
    if (i < n) { g_deg[i] = 0; g_rowcnt[i] = 0; }
    if (i < NG * 64) g_pool[i] = 0.f;
    if (i < NG) g_cnt[i] = 0;
}

// 4 edges per thread, int4-vectorized edge_index reads
__global__ void k_count(const int* __restrict__ ei, int E, int n) {
    int q = blockIdx.x * blockDim.x + threadIdx.x;
    int e = q * 4;
    if (e >= E) return;
    if (e + 4 <= E) {
        int4 sv = *(const int4*)(ei + e);
        int4 dv = *(const int4*)(ei + E + e);
        int ss[4] = {sv.x, sv.y, sv.z, sv.w};
        int dd[4] = {dv.x, dv.y, dv.z, dv.w};
#pragma unroll
        for (int j = 0; j < 4; ++j) {
            int s = ss[j], d = dd[j];
            if ((unsigned)s >= (unsigned)n || (unsigned)d >= (unsigned)n) continue;
            if (s != d) {
                atomicAdd(&g_deg[s], 1);
                atomicAdd(&g_rowcnt[d], 1);
            }
        }
    } else {
        for (; e < E; ++e) {
            int s = ei[e], d = ei[E + e];
            if ((unsigned)s >= (unsigned)n || (unsigned)d >= (unsigned)n) continue;
            if (s != d) {
                atomicAdd(&g_deg[s], 1);
                atomicAdd(&g_rowcnt[d], 1);
            }
        }
    }
}

// block sums of PADDED rowcnt + dinv + fill reset (merged)
__global__ void k_scanA(int n, int nthreads) {
    __shared__ int sh[256];
    int b = blockIdx.x, t = threadIdx.x;
    int i0 = b * 1024 + t * 4;
    int s = 0;
#pragma unroll
    for (int j = 0; j < 4; ++j)
        if (i0 + j < n) s += (g_rowcnt[i0 + j] + 1) & ~1;   // pad to even
    sh[t] = s;
    for (int i = b * 256 + t; i < n; i += nthreads) {
        int d = g_deg[i];
        g_dinv[i] = (d > 0) ? rsqrtf((float)d) : 0.f;
        g_fill[i] = 0;
    }
    __syncthreads();
    for (int off = 128; off > 0; off >>= 1) {
        if (t < off) sh[t] += sh[t + off];
        __syncthreads();
    }
    if (t == 0) g_bsum[b] = sh[0];
}

// per-block exclusive scan over PADDED counts + write padding zeros
__global__ void k_scanC(int nblocks, int n) {
    __shared__ int sh[256];
    __shared__ int soff;
    int b = blockIdx.x, t = threadIdx.x;
    if (t == 0) {
        int r = 0;
        for (int i = 0; i < b; ++i) r += g_bsum[i];
        soff = r;
    }
    int i0 = b * 1024 + t * 4;
    int v[4], pc[4];
    int s = 0;
#pragma unroll
    for (int j = 0; j < 4; ++j) {
        v[j] = (i0 + j < n) ? g_rowcnt[i0 + j] : 0;
        pc[j] = (v[j] + 1) & ~1;
        s += pc[j];
    }
    sh[t] = s;
    __syncthreads();
    for (int off = 1; off < 256; off <<= 1) {
        int add = (t >= off) ? sh[t - off] : 0;
        __syncthreads();
        sh[t] += add;
        __syncthreads();
    }
    int excl = sh[t] - s + soff;
#pragma unroll
    for (int j = 0; j < 4; ++j) {
        if (i0 + j < n) {
            g_rowptr[i0 + j] = excl;
            if (pc[j] > v[j]) g_csr[excl + v[j]] = 0u;   // padding: src=0, w=+0
        }
        excl += pc[j];
    }
    if (b == nblocks - 1 && t == 255) g_rowptr[n] = soff + sh[255];
}

// 4 edges per thread, int4-vectorized edge_index reads
__global__ void k_scatter(const int* __restrict__ ei, int E, int n) {
    int q = blockIdx.x * blockDim.x + threadIdx.x;
    int e = q * 4;
    if (e >= E) return;
    int ss[4], dd[4];
    int cnt;
    if (e + 4 <= E) {
        int4 sv = *(const int4*)(ei + e);
        int4 dv = *(const int4*)(ei + E + e);
        ss[0] = sv.x; ss[1] = sv.y; ss[2] = sv.z; ss[3] = sv.w;
        dd[0] = dv.x; dd[1] = dv.y; dd[2] = dv.z; dd[3] = dv.w;
        cnt = 4;
    } else {
        cnt = E - e;
        for (int j = 0; j < cnt; ++j) { ss[j] = ei[e + j]; dd[j] = ei[E + e + j]; }
    }
#pragma unroll
    for (int j = 0; j < 4; ++j) {
        if (j >= cnt) break;
        int s = ss[j], d = dd[j];
        if ((unsigned)s >= (unsigned)n || (unsigned)d >= (unsigned)n) continue;
        if (s == d) continue;
        float w = -g_dinv[s] * g_dinv[d];
        unsigned short wh = __half_as_ushort(__float2half_rn(w));
        unsigned enc = (unsigned)s | ((unsigned)wh << 16);
        int pos = g_rowptr[d] + atomicAdd(&g_fill[d], 1);
        g_csr[pos] = enc;
    }
}

// ---------------- fp32 SpMM (layer 1, F=4) standalone: 8-way edge split ----------
// 8 threads per node, interleaved edge split, shuffle-reduced in fp32 (exact).
template <bool RECUR>
__global__ void k_spmm4(float* __restrict__ y, const float* __restrict__ z,
                        const float* __restrict__ t0, int n) {
    int gid = blockIdx.x * blockDim.x + threadIdx.x;
    int node = gid >> 3;
    int sub = gid & 7;
    if (node >= n) return;
    int end = g_rowptr[node + 1];
    float ax = 0.f, ay = 0.f, az = 0.f, aw = 0.f;
    const float4* z4 = (const float4*)z;
    for (int e = g_rowptr[node] + sub; e < end; e += 8) {
        int s; float w;
        dec(__ldg(&g_csr[e]), s, w);
        float4 v = __ldg(&z4[s]);
        ax = fmaf(w, v.x, ax); ay = fmaf(w, v.y, ay);
        az = fmaf(w, v.z, az); aw = fmaf(w, v.w, aw);
    }
#pragma unroll
    for (int off = 4; off >= 1; off >>= 1) {
        ax += __shfl_xor_sync(0xffffffffu, ax, off);
        ay += __shfl_xor_sync(0xffffffffu, ay, off);
        az += __shfl_xor_sync(0xffffffffu, az, off);
        aw += __shfl_xor_sync(0xffffffffu, aw, off);
    }
    if (sub != 0) return;
    float4 r;
    if (RECUR) {
        float4 p = __ldg(((const float4*)t0) + node);
        r = make_float4(2.f * ax - p.x, 2.f * ay - p.y, 2.f * az - p.z, 2.f * aw - p.w);
    } else {
        r = make_float4(ax, ay, az, aw);
    }
    ((float4*)y)[node] = r;
}

// ---------------- fp32 SpMM core (F=4), 1 thread/node (used by fused kernel) ----
__device__ __forceinline__ float4 spmm4_row_rec(const float* __restrict__ z,
                                                float4 t0row, int node) {
    int beg = g_rowptr[node];            // even
    int end = g_rowptr[node + 1];        // even
    float ax = 0.f, ay = 0.f, az = 0.f, aw = 0.f;
    const float4* z4 = (const float4*)z;
    int e = beg;
    if (end - beg >= 4) {
        uint2 ca = __ldg((const uint2*)(g_csr + e));
        uint2 cb = __ldg((const uint2*)(g_csr + e + 2));
        for (; e + 8 <= end; e += 4) {
            int s0, s1, s2, s3; float w0, w1, w2, w3;
            dec(ca.x, s0, w0); dec(ca.y, s1, w1);
            dec(cb.x, s2, w2); dec(cb.y, s3, w3);
            float4 v0 = __ldg(&z4[s0]);
            float4 v1 = __ldg(&z4[s1]);
            float4 v2 = __ldg(&z4[s2]);
            float4 v3 = __ldg(&z4[s3]);
            uint2 na = __ldg((const uint2*)(g_csr + e + 4));
            uint2 nb = __ldg((const uint2*)(g_csr + e + 6));
            ax = fmaf(w0, v0.x, ax); ay = fmaf(w0, v0.y, ay);
            az = fmaf(w0, v0.z, az); aw = fmaf(w0, v0.w, aw);
            ax = fmaf(w1, v1.x, ax); ay = fmaf(w1, v1.y, ay);
            az = fmaf(w1, v1.z, az); aw = fmaf(w1, v1.w, aw);
            ax = fmaf(w2, v2.x, ax); ay = fmaf(w2, v2.y, ay);
            az = fmaf(w2, v2.z, az); aw = fmaf(w2, v2.w, aw);
            ax = fmaf(w3, v3.x, ax); ay = fmaf(w3, v3.y, ay);
            az = fmaf(w3, v3.z, az); aw = fmaf(w3, v3.w, aw);
            ca = na; cb = nb;
        }
        int s0, s1, s2, s3; float w0, w1, w2, w3;
        dec(ca.x, s0, w0); dec(ca.y, s1, w1);
        dec(cb.x, s2, w2); dec(cb.y, s3, w3);
        float4 v0 = __ldg(&z4[s0]);
        float4 v1 = __ldg(&z4[s1]);
        float4 v2 = __ldg(&z4[s2]);
        float4 v3 = __ldg(&z4[s3]);
        ax = fmaf(w0, v0.x, ax); ay = fmaf(w0, v0.y, ay);
        az = fmaf(w0, v0.z, az); aw = fmaf(w0, v0.w, aw);
        ax = fmaf(w1, v1.x, ax); ay = fmaf(w1, v1.y, ay);
        az = fmaf(w1, v1.z, az); aw = fmaf(w1, v1.w, aw);
        ax = fmaf(w2, v2.x, ax); ay = fmaf(w2, v2.y, ay);
        az = fmaf(w2, v2.z, az); aw = fmaf(w2, v2.w, aw);
        ax = fmaf(w3, v3.x, ax); ay = fmaf(w3, v3.y, ay);
        az = fmaf(w3, v3.z, az); aw = fmaf(w3, v3.w, aw);
        e += 4;
    }
    for (; e < end; ++e) {
        int s; float w;
        dec(__ldg(&g_csr[e]), s, w);
        float4 v = __ldg(&z4[s]);
        ax = fmaf(w, v.x, ax); ay = fmaf(w, v.y, ay);
        az = fmaf(w, v.z, az); aw = fmaf(w, v.w, aw);
    }
    return make_float4(2.f * ax - t0row.x, 2.f * ay - t0row.y,
                       2.f * az - t0row.z, 2.f * aw - t0row.w);
}

// ---------------- FUSED layer-1 4th SpMM + dense: h1 = relu(sum_k T_k W1_k + b)
__global__ void __launch_bounds__(256)
k_spmm4_dense(__half* __restrict__ out,
              const float* __restrict__ t0,   // x
              const float* __restrict__ t1,   // txA
              const float* __restrict__ t2,   // txB (recurrence subtrahend)
              const float* __restrict__ t3,   // txC (spmm operand)
              const float* __restrict__ W, const float* __restrict__ bias, int n) {
    constexpr int FIN = 4, FOUT = 32;
    __shared__ float sW[5 * FIN * FOUT];
    for (int i = threadIdx.x; i < 5 * FIN * FOUT; i += 256) sW[i] = W[i];
    __syncthreads();
    int node = blockIdx.x * blockDim.x + threadIdx.x;
    if (node >= n) return;
    float4 T2 = __ldg(((const float4*)t2) + node);
    float4 T4 = spmm4_row_rec(t3, T2, node);
    float4 T[5];
    T[0] = __ldg(((const float4*)t0) + node);
    T[1] = __ldg(((const float4*)t1) + node);
    T[2] = T2;
    T[3] = __ldg(((const float4*)t3) + node);
    T[4] = T4;
    unsigned long long acc[FOUT / 2];
#pragma unroll
    for (int j = 0; j < FOUT / 2; ++j) acc[j] = pk2(bias[2 * j], bias[2 * j + 1]);
    const unsigned long long* sW2 = (const unsigned long long*)sW;
#pragma unroll
    for (int k = 0; k < 5; ++k) {
        unsigned long long tb0 = pk2(T[k].x, T[k].x);
        unsigned long long tb1 = pk2(T[k].y, T[k].y);
        unsigned long long tb2 = pk2(T[k].z, T[k].z);
        unsigned long long tb3 = pk2(T[k].w, T[k].w);
        const unsigned long long* w0 = sW2 + (size_t)(k * FIN + 0) * (FOUT / 2);
        const unsigned long long* w1 = sW2 + (size_t)(k * FIN + 1) * (FOUT / 2);
        const unsigned long long* w2 = sW2 + (size_t)(k * FIN + 2) * (FOUT / 2);
        const unsigned long long* w3 = sW2 + (size_t)(k * FIN + 3) * (FOUT / 2);
#pragma unroll
        for (int j = 0; j < FOUT / 2; ++j) {
            fma2(acc[j], w0[j], tb0);
            fma2(acc[j], w1[j], tb1);
            fma2(acc[j], w2[j], tb2);
            fma2(acc[j], w3[j], tb3);
        }
    }
    uint4 o[FOUT / 8];
#pragma unroll
    for (int j = 0; j < FOUT / 2; ++j) {
        float2 v = up2(acc[j]);
        v.x = fmaxf(v.x, 0.f);
        v.y = fmaxf(v.y, 0.f);
        ((unsigned int*)o)[j] = f2h(v);
    }
    uint4* orow = (uint4*)(out + (size_t)node * FOUT);
#pragma unroll
    for (int j4 = 0; j4 < FOUT / 8; ++j4) orow[j4] = o[j4];
}

// ---------------- fp16 SpMM: y = L z  or  2 L z - t0 ----------------
// F/8 lanes per node, one uint4 (16B, 8 halves) per lane. CSR read as aligned
// uint2 pairs (rows even-padded); single-stage csr prefetch pipeline.
template <int F, bool RECUR>
__global__ void k_spmmh(__half* __restrict__ y, const __half* __restrict__ z,
                        const __half* __restrict__ t0, int n) {
    constexpr int L = F / 8;
    int gid = blockIdx.x * blockDim.x + threadIdx.x;
    int node = gid / L;
    int lane = gid - node * L;
    if (node >= n) return;
    int beg = g_rowptr[node];            // even
    int end = g_rowptr[node + 1];        // even
    unsigned long long a0 = 0ull, a1 = 0ull, a2 = 0ull, a3 = 0ull;
    const uint4* z4 = (const uint4*)z;
    int e = beg;
    if (end - beg >= 4) {
        uint2 ca = __ldg((const uint2*)(g_csr + e));
        uint2 cb = __ldg((const uint2*)(g_csr + e + 2));
        for (; e + 8 <= end; e += 4) {
            int s0, s1, s2, s3; float w0, w1, w2, w3;
            dec(ca.x, s0, w0); dec(ca.y, s1, w1);
            dec(cb.x, s2, w2); dec(cb.y, s3, w3);
            uint4 v0 = __ldg(&z4[(size_t)s0 * L + lane]);
            uint4 v1 = __ldg(&z4[(size_t)s1 * L + lane]);
            uint4 v2 = __ldg(&z4[(size_t)s2 * L + lane]);
            uint4 v3 = __ldg(&z4[(size_t)s3 * L + lane]);
            uint2 na = __ldg((const uint2*)(g_csr + e + 4));
            uint2 nb = __ldg((const uint2*)(g_csr + e + 6));
            acc8(a0, a1, a2, a3, v0, w0);
            acc8(a0, a1, a2, a3, v1, w1);
            acc8(a0, a1, a2, a3, v2, w2);
            acc8(a0, a1, a2, a3, v3, w3);
            ca = na; cb = nb;
        }
        int s0, s1, s2, s3; float w0, w1, w2, w3;
        dec(ca.x, s0, w0); dec(ca.y, s1, w1);
        dec(cb.x, s2, w2); dec(cb.y, s3, w3);
        uint4 v0 = __ldg(&z4[(size_t)s0 * L + lane]);
        uint4 v1 = __ldg(&z4[(size_t)s1 * L + lane]);
        uint4 v2 = __ldg(&z4[(size_t)s2 * L + lane]);
        uint4 v3 = __ldg(&z4[(size_t)s3 * L + lane]);
        acc8(a0, a1, a2, a3, v0, w0);
        acc8(a0, a1, a2, a3, v1, w1);
        acc8(a0, a1, a2, a3, v2, w2);
        acc8(a0, a1, a2, a3, v3, w3);
        e += 4;
    }
    if (e < end) {                        // exactly 2 remaining (even padding)
        uint2 c = __ldg((const uint2*)(g_csr + e));
        int s0, s1; float w0, w1;
        dec(c.x, s0, w0); dec(c.y, s1, w1);
        uint4 v0 = __ldg(&z4[(size_t)s0 * L + lane]);
        uint4 v1 = __ldg(&z4[(size_t)s1 * L + lane]);
        acc8(a0, a1, a2, a3, v0, w0);
        acc8(a0, a1, a2, a3, v1, w1);
    }
    size_t o = (size_t)node * L + lane;
    float2 r0 = up2(a0), r1 = up2(a1), r2 = up2(a2), r3 = up2(a3);
    if (RECUR) {
        uint4 p = __ldg(((const uint4*)t0) + o);
        float2 q0 = h2f(p.x), q1 = h2f(p.y), q2 = h2f(p.z), q3 = h2f(p.w);
        r0.x = 2.f * r0.x - q0.x; r0.y = 2.f * r0.y - q0.y;
        r1.x = 2.f * r1.x - q1.x; r1.y = 2.f * r1.y - q1.y;
        r2.x = 2.f * r2.x - q2.x; r2.y = 2.f * r2.y - q2.y;
        r3.x = 2.f * r3.x - q3.x; r3.y = 2.f * r3.y - q3.y;
    }
    uint4 w;
    w.x = f2h(r0); w.y = f2h(r1); w.z = f2h(r2); w.w = f2h(r3);
    ((uint4*)y)[o] = w;
}

// ---------------- fused 5-term dense, fp16 in: out = relu(sum_k T_k @ W_k + b) ------
// POOL: red.v2 relu(acc) into g_pool / g_cnt (global mean pool), no row store.
template <int FIN, int FOUT, bool POOL>
__global__ void __launch_bounds__(128)
k_dense5h(__half* __restrict__ out,
          const __half* __restrict__ t0, const __half* __restrict__ t1,
          const __half* __restrict__ t2, const __half* __restrict__ t3,
          const __half* __restrict__ t4,
          const float* __restrict__ W, const float* __restrict__ bias,
          const int* __restrict__ batch, int n) {
    __shared__ float sW[FIN * FOUT];
    const __half* tx[5] = {t0, t1, t2, t3, t4};
    int node = blockIdx.x * 128 + threadIdx.x;
    unsigned long long acc[FOUT / 2];
    if (node < n) {
#pragma unroll
        for (int j = 0; j < FOUT / 2; ++j) acc[j] = pk2(bias[2 * j], bias[2 * j + 1]);
    }
#pragma unroll
    for (int k = 0; k < 5; ++k) {
        __syncthreads();
        for (int i = threadIdx.x; i < FIN * FOUT; i += 128) sW[i] = W[k * FIN * FOUT + i];
        __syncthreads();
        if (node < n) {
            const uint4* trow = (const uint4*)(tx[k] + (size_t)node * FIN);
            const unsigned long long* sW2 = (const unsigned long long*)sW;
#pragma unroll 2
            for (int i8 = 0; i8 < FIN / 8; ++i8) {
                uint4 v = __ldg(&trow[i8]);
                float2 f0 = h2f(v.x), f1 = h2f(v.y), f2 = h2f(v.z), f3 = h2f(v.w);
                unsigned long long tb[8];
                tb[0] = pk2(f0.x, f0.x); tb[1] = pk2(f0.y, f0.y);
                tb[2] = pk2(f1.x, f1.x); tb[3] = pk2(f1.y, f1.y);
                tb[4] = pk2(f2.x, f2.x); tb[5] = pk2(f2.y, f2.y);
                tb[6] = pk2(f3.x, f3.x); tb[7] = pk2(f3.y, f3.y);
#pragma unroll
                for (int v8 = 0; v8 < 8; ++v8) {
                    const unsigned long long* wr =
                        sW2 + (size_t)(8 * i8 + v8) * (FOUT / 2);
#pragma unroll
                    for (int j = 0; j < FOUT / 2; ++j) fma2(acc[j], wr[j], tb[v8]);
                }
            }
        }
    }
    if (node >= n) return;
    if (POOL) {
        int g = batch[node];
        if ((unsigned)g >= NG) return;
        float* pg = &g_pool[g * FOUT];
#pragma unroll
        for (int j = 0; j < FOUT / 2; ++j) {
            float2 v = up2(acc[j]);
            float vx = fmaxf(v.x, 0.f);
            float vy = fmaxf(v.y, 0.f);
            asm volatile("red.global.add.v2.f32 [%0], {%1, %2};"
                         :: "l"(pg + 2 * j), "f"(vx), "f"(vy) : "memory");
        }
        atomicAdd(&g_cnt[g], 1);
    } else {
        uint4 o[FOUT / 8];
#pragma unroll
        for (int j = 0; j < FOUT / 2; ++j) {
            float2 v = up2(acc[j]);
            v.x = fmaxf(v.x, 0.f);
            v.y = fmaxf(v.y, 0.f);
            ((unsigned int*)o)[j] = f2h(v);
        }
        uint4* orow = (uint4*)(out + (size_t)node * FOUT);
#pragma unroll
        for (int j4 = 0; j4 < FOUT / 8; ++j4) orow[j4] = o[j4];
    }
}

// ---------------- final MLP over pooled means ----------------
__global__ void k_fc(const float* __restrict__ w1, const float* __restrict__ b1,
                     const float* __restrict__ w2, const float* __restrict__ b2,
                     float* __restrict__ out, int G) {
    int g = threadIdx.x;
    if (g >= G) return;
    float c = (float)g_cnt[g];
    if (c < 1.f) c = 1.f;
    float m[64];
#pragma unroll
    for (int i = 0; i < 64; ++i) m[i] = g_pool[g * 64 + i] / c;
    float o = b2[0];
    for (int j = 0; j < 32; ++j) {
        float a = b1[j];
#pragma unroll
        for (int i = 0; i < 64; ++i) a = fmaf(m[i], w1[i * 32 + j], a);
        a = fmaxf(a, 0.f);
        o = fmaf(a, w2[j], o);
    }
    out[g] = o;
}

// ---------------- host ----------------
extern "C" void kernel_launch(void* const* d_in, const int* in_sizes, int n_in,
                              void* d_out, int out_size) {
    const float* x     = (const float*)d_in[0];
    const int*   ei    = (const int*)d_in[1];     // int32 (JAX x64 disabled)
    const int*   batch = (const int*)d_in[2];

    int wi = 3;
    while (wi < n_in && in_sizes[wi] != 640) ++wi;
    const float* W1   = (const float*)d_in[wi + 0];
    const float* b1   = (const float*)d_in[wi + 1];
    const float* W2   = (const float*)d_in[wi + 2];
    const float* b2   = (const float*)d_in[wi + 3];
    const float* W3   = (const float*)d_in[wi + 4];
    const float* b3   = (const float*)d_in[wi + 5];
    const float* fcw1 = (const float*)d_in[wi + 6];
    const float* fcb1 = (const float*)d_in[wi + 7];
    const float* fcw2 = (const float*)d_in[wi + 8];
    const float* fcb2 = (const float*)d_in[wi + 9];

    int n = in_sizes[0] / 4;
    int E = in_sizes[1] / 2;
    float* out = (float*)d_out;

    float *t32A, *t32B, *t32C;
    __half *txA, *txB, *txC, *txD, *h1, *h2;
    cudaGetSymbolAddress((void**)&t32A, g_t32A);
    cudaGetSymbolAddress((void**)&t32B, g_t32B);
    cudaGetSymbolAddress((void**)&t32C, g_t32C);
    cudaGetSymbolAddress((void**)&txA, g_txA);
    cudaGetSymbolAddress((void**)&txB, g_txB);
    cudaGetSymbolAddress((void**)&txC, g_txC);
    cudaGetSymbolAddress((void**)&txD, g_txD);
    cudaGetSymbolAddress((void**)&h1,  g_h1);
    cudaGetSymbolAddress((void**)&h2,  g_h2);

    const int TB = 256;
    int gN = (n + TB - 1) / TB;
    int gE4 = ((E + 3) / 4 + TB - 1) / TB;   // 4 edges/thread
    int gD = (n + 127) / 128;
    int gScan = (n + 1023) / 1024;

    // ---- preprocessing: degree, dinv, even-padded CSR build ----
    k_zero<<<gN, TB>>>(n);
    k_count<<<gE4, TB>>>(ei, E, n);
    k_scanA<<<gScan, 256>>>(n, gScan * 256);
    k_scanC<<<gScan, 256>>>(gScan, n);
    k_scatter<<<gE4, TB>>>(ei, E, n);

    // ---- layer 1: FIN=4 (fp32), FOUT=32 -> h1 (fp16); 4th SpMM fused with dense ----
    {
        int gS = (n * 8 + TB - 1) / TB;   // 8 edge-split threads per node
        k_spmm4<false><<<gS, TB>>>(t32A, x,    x,    n);
        k_spmm4<true ><<<gS, TB>>>(t32B, t32A, x,    n);
        k_spmm4<true ><<<gS, TB>>>(t32C, t32B, t32A, n);
        k_spmm4_dense<<<gN, TB>>>(h1, x, t32A, t32B, t32C, W1, b1, n);
    }

    // ---- layer 2: FIN=32 (fp16), FOUT=64 -> h2 (fp16) ----
    {
        int gS = (n * 4 + TB - 1) / TB;   // L = 32/8 = 4 lanes/node
        k_spmmh<32, false><<<gS, TB>>>(txA, h1,  h1,  n);
        k_spmmh<32, true ><<<gS, TB>>>(txB, txA, h1,  n);
        k_spmmh<32, true ><<<gS, TB>>>(txC, txB, txA, n);
        k_spmmh<32, true ><<<gS, TB>>>(txD, txC, txB, n);
        k_dense5h<32, 64, false><<<gD, 128>>>(h2, h1, txA, txB, txC, txD, W2, b2, batch, n);
    }

    // ---- layer 3: FIN=64 (fp16), FOUT=64, fused global mean pool ----
    {
        int gS = (n * 8 + TB - 1) / TB;   // L = 64/8 = 8 lanes/node
        k_spmmh<64, false><<<gS, TB>>>(txA, h2,  h2,  n);
        k_spmmh<64, true ><<<gS, TB>>>(txB, txA, h2,  n);
        k_spmmh<64, true ><<<gS, TB>>>(txC, txB, txA, n);
        k_spmmh<64, true ><<<gS, TB>>>(txD, txC, txB, n);
        k_dense5h<64, 64, true><<<gD, 128>>>(nullptr, h2, txA, txB, txC, txD, W3, b3, batch, n);
    }

    // ---- MLP head ----
    k_fc<<<1, 128>>>(fcw1, fcb1, fcw2, fcb2, out, out_size);
}